// round 14
// baseline (speedup 1.0000x reference)
#include <cuda_runtime.h>
#include <cuda_fp16.h>
#include <cstdint>
#include <math.h>

// Problem constants: B=4096, OUT=1024, IN=1024
#define BATCH 4096
#define OUTF  1024
#define INF   1024
#define KTOT  3072            // 3 * INF (x | x^2 | x^3 concatenated on K)
#define BN_EPS 1e-5f
#define GRID_CTAS 128

// ---------------------------------------------------------------------------
// Scratch (__device__ globals; no allocations allowed)
// ---------------------------------------------------------------------------
__device__ __half g_A[(size_t)BATCH * KTOT];   // 24 MB: [x | x^2 | x^3] fp16
__device__ __half g_B[(size_t)OUTF * KTOT];    //  6 MB: [c1 | c2 | c3] fp16
__device__ float g_psum[32][OUTF];
__device__ float g_psqsum[32][OUTF];
__device__ unsigned int g_bar = 0;             // monotonic grid-barrier ticket

// ---------------------------------------------------------------------------
// Baseline-PTX helpers (sm_80 features only: harness compiles via compute_103)
// ---------------------------------------------------------------------------
__device__ __forceinline__ uint32_t smem_u32(const void* p) {
    uint32_t a;
    asm("{ .reg .u64 t; cvta.to.shared.u64 t, %1; cvt.u32.u64 %0, t; }" : "=r"(a) : "l"(p));
    return a;
}
__device__ __forceinline__ void cp16(uint32_t dst, const void* src) {
    asm volatile("cp.async.cg.shared.global [%0], [%1], 16;" :: "r"(dst), "l"(src));
}
__device__ __forceinline__ uint32_t pack_h2(float lo, float hi) {
    __half2 h = __floats2half2_rn(lo, hi);
    return *reinterpret_cast<uint32_t*>(&h);
}
__device__ __forceinline__ unsigned int ld_acquire_gpu(const unsigned int* p) {
    unsigned int v;
    asm volatile("ld.acquire.gpu.u32 %0, [%1];" : "=r"(v) : "l"(p) : "memory");
    return v;
}

// m16n8k16 fp16 tensor-core MMA (sm_80 baseline PTX), fp32 accumulate
#define MMA_F16(d, a, b) \
    asm volatile("mma.sync.aligned.m16n8k16.row.col.f32.f16.f16.f32 " \
        "{%0,%1,%2,%3}, {%4,%5,%6,%7}, {%8,%9}, {%0,%1,%2,%3};" \
        : "+f"((d)[0]), "+f"((d)[1]), "+f"((d)[2]), "+f"((d)[3]) \
        : "r"((a)[0]), "r"((a)[1]), "r"((a)[2]), "r"((a)[3]), \
          "r"((b)[0]), "r"((b)[1]))

// ldmatrix m8n8.x4 (sm_75+ baseline PTX)
#define LDSM_X4(r0, r1, r2, r3, addr) \
    asm volatile("ldmatrix.sync.aligned.m8n8.x4.shared.b16 {%0,%1,%2,%3}, [%4];" \
        : "=r"(r0), "=r"(r1), "=r"(r2), "=r"(r3) : "r"(addr))

// ---------------------------------------------------------------------------
// Pre-pass: pack A = [x|x^2|x^3] and B = [c1|c2|c3] as fp16.
// Blocks [0,4096) -> A; [4096,5120) -> B.
// ---------------------------------------------------------------------------
__global__ __launch_bounds__(256)
void pack_kernel(const float* __restrict__ X,
                 const float* __restrict__ C1,
                 const float* __restrict__ C2,
                 const float* __restrict__ C3)
{
    if (blockIdx.x < 4096) {
        const int idx = blockIdx.x * 256 + threadIdx.x;
        const int b  = idx >> 8;
        const int k4 = (idx & 255) * 4;
        const float4 v = *reinterpret_cast<const float4*>(X + (size_t)b * INF + k4);
        float4 s, c;
        s.x = v.x * v.x; s.y = v.y * v.y; s.z = v.z * v.z; s.w = v.w * v.w;
        c.x = s.x * v.x; c.y = s.y * v.y; c.z = s.z * v.z; c.w = s.w * v.w;
        __half* rowp = g_A + (size_t)b * KTOT;
        uint2 h;
        h.x = pack_h2(v.x, v.y); h.y = pack_h2(v.z, v.w);
        *reinterpret_cast<uint2*>(rowp + k4) = h;
        h.x = pack_h2(s.x, s.y); h.y = pack_h2(s.z, s.w);
        *reinterpret_cast<uint2*>(rowp + INF + k4) = h;
        h.x = pack_h2(c.x, c.y); h.y = pack_h2(c.z, c.w);
        *reinterpret_cast<uint2*>(rowp + 2 * INF + k4) = h;
    } else {
        const int idx = (blockIdx.x - 4096) * 256 + threadIdx.x;
        const int o  = idx >> 8;
        const int k4 = (idx & 255) * 4;
        const size_t src = (size_t)o * INF + k4;
        __half* rowp = g_B + (size_t)o * KTOT;
        float4 v; uint2 h;
        v = *reinterpret_cast<const float4*>(C1 + src);
        h.x = pack_h2(v.x, v.y); h.y = pack_h2(v.z, v.w);
        *reinterpret_cast<uint2*>(rowp + k4) = h;
        v = *reinterpret_cast<const float4*>(C2 + src);
        h.x = pack_h2(v.x, v.y); h.y = pack_h2(v.z, v.w);
        *reinterpret_cast<uint2*>(rowp + INF + k4) = h;
        v = *reinterpret_cast<const float4*>(C3 + src);
        h.x = pack_h2(v.x, v.y); h.y = pack_h2(v.z, v.w);
        *reinterpret_cast<uint2*>(rowp + 2 * INF + k4) = h;
    }
}

// ---------------------------------------------------------------------------
// Fully fused: fp16 GEMM (M=4096,N=1024,K=3072) + BN stats + grid barrier +
// BN finalize + normalized store.
// CTA tile 128x256, 512 threads = 16 warps (2m x 8n), warp tile 64x32.
// KCH=64 (4 k16 slabs), 3-stage cp.async pipeline (halves sync count vs R11),
// register-level fragment pipelining across slabs (hides LDSM latency).
// Grid = (4,32) = 128 CTAs at 1 CTA/SM -> co-resident; grid barrier safe.
// ---------------------------------------------------------------------------
#define TILE_M 128
#define TILE_N 256
#define KCH    64
#define NCHUNK (KTOT / KCH)        // 48
#define RBB    144                 // bytes per smem row (128 data + 16 pad)
#define MATB_A (128 * RBB)         // 18432 B
#define MATB_B (256 * RBB)         // 36864 B
#define STAGEB (MATB_A + MATB_B)   // 55296 B
#define SMEM_BYTES (3 * STAGEB)    // 165888 B

__global__ __launch_bounds__(512, 1)
void poly_mma_bn_kernel(float* __restrict__ Y,
                        const float* __restrict__ gamma,
                        const float* __restrict__ beta)
{
    extern __shared__ char sm[];
    const uint32_t smbase = smem_u32(sm);

    const int tid  = threadIdx.x;
    const int wid  = tid >> 5;
    const int lane = tid & 31;
    const int g    = lane >> 2;      // 0..7
    const int tig  = lane & 3;       // 0..3
    const int warp_m = wid >> 3;     // 0..1  -> m base = warp_m*64
    const int warp_n = wid & 7;      // 0..7  -> n base = warp_n*32

    const int block_o = blockIdx.x * TILE_N;
    const int block_b = blockIdx.y * TILE_M;

    // ldmatrix per-lane address components
    const int quad = lane >> 3;
    const int rq   = lane & 7;
    const uint32_t a_lane_off = (uint32_t)((((quad & 1) * 8) + rq) * RBB + (quad >> 1) * 16);
    const uint32_t b_lane_off = (uint32_t)((((quad >> 1) * 8) + rq) * RBB + (quad & 1) * 16);

    // cp.async geometry (512 threads, KCH=64 -> 128B data per row):
    //   A: 128 rows x 8 16B pieces = 1024 -> 2 per thread (pieces qc, qc+4)
    //   B: 256 rows x 8 pieces = 2048 -> 4 per thread (rows r, r+128)
    const int crow = tid >> 2;          // 0..127
    const int qc   = tid & 3;
    const __half* srcA  = g_A + (size_t)(block_b + crow) * KTOT + qc * 8;
    const __half* srcB0 = g_B + (size_t)(block_o + crow) * KTOT + qc * 8;
    const __half* srcB1 = g_B + (size_t)(block_o + crow + 128) * KTOT + qc * 8;
    const uint32_t cdst = (uint32_t)(crow * RBB + qc * 16);

    float acc[4][4][4];
    #pragma unroll
    for (int mt = 0; mt < 4; mt++)
        #pragma unroll
        for (int nt = 0; nt < 4; nt++)
            #pragma unroll
            for (int r = 0; r < 4; r++)
                acc[mt][nt][r] = 0.0f;

    auto stage_chunk = [&](int s) {
        if (s < NCHUNK) {
            const uint32_t base = smbase + (uint32_t)((s % 3) * STAGEB);
            const int k0 = s * KCH;
            cp16(base + cdst,      srcA + k0);
            cp16(base + cdst + 64, srcA + k0 + 32);
            const uint32_t bB = base + MATB_A;
            cp16(bB + cdst,                  srcB0 + k0);
            cp16(bB + cdst + 64,             srcB0 + k0 + 32);
            cp16(bB + cdst + 128 * RBB,      srcB1 + k0);
            cp16(bB + cdst + 128 * RBB + 64, srcB1 + k0 + 32);
        }
        asm volatile("cp.async.commit_group;" ::: "memory");
    };

    stage_chunk(0);
    stage_chunk(1);

    const uint32_t a_warp = (uint32_t)(warp_m * 64 * RBB) + a_lane_off;
    const uint32_t b_warp = (uint32_t)(warp_n * 32 * RBB) + b_lane_off;

    for (int s = 0; s < NCHUNK; ++s) {
        asm volatile("cp.async.wait_group 1;" ::: "memory");
        __syncthreads();

        stage_chunk(s + 2);   // buffer (s+2)%3 == (s-1)%3: freed last iteration

        const uint32_t stA = smbase + (uint32_t)((s % 3) * STAGEB) + a_warp;
        const uint32_t stB = smbase + (uint32_t)((s % 3) * STAGEB) + MATB_A + b_warp;

        // register-pipelined fragments: two sets, load kk+1 before MMA of kk
        uint32_t aF[2][4][4], bF[2][4][2];

        // load slab 0 fragments
        #pragma unroll
        for (int mt = 0; mt < 4; mt++)
            LDSM_X4(aF[0][mt][0], aF[0][mt][1], aF[0][mt][2], aF[0][mt][3],
                    stA + (uint32_t)(mt * 16 * RBB));
        #pragma unroll
        for (int p = 0; p < 2; p++)
            LDSM_X4(bF[0][2 * p][0], bF[0][2 * p][1], bF[0][2 * p + 1][0], bF[0][2 * p + 1][1],
                    stB + (uint32_t)(p * 16 * RBB));

        #pragma unroll
        for (int kk = 0; kk < 4; kk++) {
            const int cur = kk & 1;
            const int nxt = cur ^ 1;
            if (kk < 3) {
                const uint32_t kb = (uint32_t)((kk + 1) * 32);
                #pragma unroll
                for (int mt = 0; mt < 4; mt++)
                    LDSM_X4(aF[nxt][mt][0], aF[nxt][mt][1], aF[nxt][mt][2], aF[nxt][mt][3],
                            stA + (uint32_t)(mt * 16 * RBB) + kb);
                #pragma unroll
                for (int p = 0; p < 2; p++)
                    LDSM_X4(bF[nxt][2 * p][0], bF[nxt][2 * p][1],
                            bF[nxt][2 * p + 1][0], bF[nxt][2 * p + 1][1],
                            stB + (uint32_t)(p * 16 * RBB) + kb);
            }
            #pragma unroll
            for (int mt = 0; mt < 4; mt++)
                #pragma unroll
                for (int nt = 0; nt < 4; nt++)
                    MMA_F16(acc[mt][nt], aF[cur][mt], bF[cur][nt]);
        }
    }

    // ---- phase 1: BN partial stats for this 128-row block (registers only)
    float csum[4][2], csq[4][2];
    #pragma unroll
    for (int nt = 0; nt < 4; nt++)
        #pragma unroll
        for (int c = 0; c < 2; c++) {
            float s0 = 0.0f, q0 = 0.0f;
            #pragma unroll
            for (int mt = 0; mt < 4; mt++) {
                const float vlo = acc[mt][nt][c];
                const float vhi = acc[mt][nt][c + 2];
                s0 += vlo + vhi;
                q0 = fmaf(vlo, vlo, q0);
                q0 = fmaf(vhi, vhi, q0);
            }
            csum[nt][c] = s0;
            csq[nt][c] = q0;
        }
    #pragma unroll
    for (int d = 4; d <= 16; d <<= 1) {
        #pragma unroll
        for (int nt = 0; nt < 4; nt++)
            #pragma unroll
            for (int c = 0; c < 2; c++) {
                csum[nt][c] += __shfl_xor_sync(0xFFFFFFFFu, csum[nt][c], d);
                csq[nt][c]  += __shfl_xor_sync(0xFFFFFFFFu, csq[nt][c], d);
            }
    }
    float* red_sum = reinterpret_cast<float*>(sm);          // [2][256]
    float* red_sq  = reinterpret_cast<float*>(sm) + 512;    // [2][256]
    __syncthreads();
    if (g == 0) {
        #pragma unroll
        for (int nt = 0; nt < 4; nt++)
            #pragma unroll
            for (int c = 0; c < 2; c++) {
                const int col = warp_n * 32 + nt * 8 + 2 * tig + c;
                red_sum[warp_m * 256 + col] = csum[nt][c];
                red_sq [warp_m * 256 + col] = csq[nt][c];
            }
    }
    __syncthreads();
    if (tid < 256) {
        g_psum[blockIdx.y][block_o + tid]   = red_sum[tid] + red_sum[256 + tid];
        g_psqsum[blockIdx.y][block_o + tid] = red_sq[tid]  + red_sq[256 + tid];
    }

    // ---- phase 2: grid barrier (replay-safe monotonic ticket).
    // All 128 CTAs co-resident (1 CTA/SM, 128 <= #SMs) -> no deadlock.
    __threadfence();
    __syncthreads();
    if (tid == 0) {
        const unsigned int ticket = atomicAdd(&g_bar, 1u);
        const unsigned int target = (ticket / GRID_CTAS + 1u) * GRID_CTAS;
        while (ld_acquire_gpu(&g_bar) < target) { }
    }
    __syncthreads();

    // ---- phase 3: per-column affine for this CTA's 256 columns
    float* smc = reinterpret_cast<float*>(sm);          // scale [256]
    float* smh = reinterpret_cast<float*>(sm) + 256;    // shift [256]
    if (tid < 256) {
        const int col = block_o + tid;
        float S = 0.0f, SS = 0.0f;
        #pragma unroll
        for (int i = 0; i < 32; i++) { S += g_psum[i][col]; SS += g_psqsum[i][col]; }
        const float inv_n = 1.0f / (float)BATCH;
        const float mean = S * inv_n;
        const float var  = SS * inv_n - mean * mean;
        const float rstd = rsqrtf(var + BN_EPS);
        const float sc = rstd * gamma[col];
        smc[tid] = sc;
        smh[tid] = fmaf(-mean, sc, beta[col]);
    }
    __syncthreads();

    // ---- phase 4: normalize accumulators and store Y once
    #pragma unroll
    for (int mt = 0; mt < 4; mt++) {
        #pragma unroll
        for (int nt = 0; nt < 4; nt++) {
            const int colT = warp_n * 32 + nt * 8 + 2 * tig;
            const float scx = smc[colT],     scy = smc[colT + 1];
            const float shx = smh[colT],     shy = smh[colT + 1];
            const int row = block_b + warp_m * 64 + mt * 16 + g;
            const int col = block_o + colT;
            float2 lo = make_float2(fmaf(acc[mt][nt][0], scx, shx),
                                    fmaf(acc[mt][nt][1], scy, shy));
            float2 hi = make_float2(fmaf(acc[mt][nt][2], scx, shx),
                                    fmaf(acc[mt][nt][3], scy, shy));
            *reinterpret_cast<float2*>(Y + (size_t)row * OUTF + col) = lo;
            *reinterpret_cast<float2*>(Y + (size_t)(row + 8) * OUTF + col) = hi;
        }
    }
}

// ---------------------------------------------------------------------------
// Launcher. Inputs: x, c1, c2, c3, bias(skipped: cancels under BN), gamma, beta
// ---------------------------------------------------------------------------
extern "C" void kernel_launch(void* const* d_in, const int* in_sizes, int n_in,
                              void* d_out, int out_size)
{
    (void)in_sizes; (void)n_in; (void)out_size;
    const float* x     = (const float*)d_in[0];
    const float* c1    = (const float*)d_in[1];
    const float* c2    = (const float*)d_in[2];
    const float* c3    = (const float*)d_in[3];
    const float* gamma = (const float*)d_in[5];
    const float* beta  = (const float*)d_in[6];
    float* y = (float*)d_out;

    cudaFuncSetAttribute(poly_mma_bn_kernel,
                         cudaFuncAttributeMaxDynamicSharedMemorySize, SMEM_BYTES);

    pack_kernel<<<4096 + 1024, 256>>>(x, c1, c2, c3);

    dim3 grid(OUTF / TILE_N, BATCH / TILE_M);   // (4, 32) = 128 CTAs
    poly_mma_bn_kernel<<<grid, 512, SMEM_BYTES>>>(y, gamma, beta);
}

// round 15
// speedup vs baseline: 1.0596x; 1.0596x over previous
#include <cuda_runtime.h>
#include <cuda_fp16.h>
#include <cstdint>
#include <math.h>

// Problem constants: B=4096, OUT=1024, IN=1024
#define BATCH 4096
#define OUTF  1024
#define INF   1024
#define KTOT  3072            // 3 * INF (x | x^2 | x^3 concatenated on K)
#define BN_EPS 1e-5f
#define GRID_CTAS 128

// ---------------------------------------------------------------------------
// Scratch (__device__ globals; no allocations allowed)
// ---------------------------------------------------------------------------
__device__ __half g_A[(size_t)BATCH * KTOT];   // 24 MB: [x | x^2 | x^3] fp16
__device__ __half g_B[(size_t)OUTF * KTOT];    //  6 MB: [c1 | c2 | c3] fp16
__device__ float g_psum[32][OUTF];
__device__ float g_psqsum[32][OUTF];
__device__ unsigned int g_bar = 0;             // monotonic grid-barrier ticket

// ---------------------------------------------------------------------------
// Baseline-PTX helpers (sm_80 features only: harness compiles via compute_103)
// ---------------------------------------------------------------------------
__device__ __forceinline__ uint32_t smem_u32(const void* p) {
    uint32_t a;
    asm("{ .reg .u64 t; cvta.to.shared.u64 t, %1; cvt.u32.u64 %0, t; }" : "=r"(a) : "l"(p));
    return a;
}
__device__ __forceinline__ void cp16(uint32_t dst, const void* src) {
    asm volatile("cp.async.cg.shared.global [%0], [%1], 16;" :: "r"(dst), "l"(src));
}
__device__ __forceinline__ uint32_t pack_h2(float lo, float hi) {
    __half2 h = __floats2half2_rn(lo, hi);
    return *reinterpret_cast<uint32_t*>(&h);
}
__device__ __forceinline__ unsigned int ld_acquire_gpu(const unsigned int* p) {
    unsigned int v;
    asm volatile("ld.acquire.gpu.u32 %0, [%1];" : "=r"(v) : "l"(p) : "memory");
    return v;
}

// m16n8k16 fp16 tensor-core MMA (sm_80 baseline PTX), fp32 accumulate
#define MMA_F16(d, a, b) \
    asm volatile("mma.sync.aligned.m16n8k16.row.col.f32.f16.f16.f32 " \
        "{%0,%1,%2,%3}, {%4,%5,%6,%7}, {%8,%9}, {%0,%1,%2,%3};" \
        : "+f"((d)[0]), "+f"((d)[1]), "+f"((d)[2]), "+f"((d)[3]) \
        : "r"((a)[0]), "r"((a)[1]), "r"((a)[2]), "r"((a)[3]), \
          "r"((b)[0]), "r"((b)[1]))

// ldmatrix m8n8.x4 (sm_75+ baseline PTX)
#define LDSM_X4(r0, r1, r2, r3, addr) \
    asm volatile("ldmatrix.sync.aligned.m8n8.x4.shared.b16 {%0,%1,%2,%3}, [%4];" \
        : "=r"(r0), "=r"(r1), "=r"(r2), "=r"(r3) : "r"(addr))

// ---------------------------------------------------------------------------
// Pre-pass: pack A = [x|x^2|x^3] and B = [c1|c2|c3] as fp16.
// Blocks [0,4096) -> A; [4096,5120) -> B.
// ---------------------------------------------------------------------------
__global__ __launch_bounds__(256)
void pack_kernel(const float* __restrict__ X,
                 const float* __restrict__ C1,
                 const float* __restrict__ C2,
                 const float* __restrict__ C3)
{
    if (blockIdx.x < 4096) {
        const int idx = blockIdx.x * 256 + threadIdx.x;
        const int b  = idx >> 8;
        const int k4 = (idx & 255) * 4;
        const float4 v = *reinterpret_cast<const float4*>(X + (size_t)b * INF + k4);
        float4 s, c;
        s.x = v.x * v.x; s.y = v.y * v.y; s.z = v.z * v.z; s.w = v.w * v.w;
        c.x = s.x * v.x; c.y = s.y * v.y; c.z = s.z * v.z; c.w = s.w * v.w;
        __half* rowp = g_A + (size_t)b * KTOT;
        uint2 h;
        h.x = pack_h2(v.x, v.y); h.y = pack_h2(v.z, v.w);
        *reinterpret_cast<uint2*>(rowp + k4) = h;
        h.x = pack_h2(s.x, s.y); h.y = pack_h2(s.z, s.w);
        *reinterpret_cast<uint2*>(rowp + INF + k4) = h;
        h.x = pack_h2(c.x, c.y); h.y = pack_h2(c.z, c.w);
        *reinterpret_cast<uint2*>(rowp + 2 * INF + k4) = h;
    } else {
        const int idx = (blockIdx.x - 4096) * 256 + threadIdx.x;
        const int o  = idx >> 8;
        const int k4 = (idx & 255) * 4;
        const size_t src = (size_t)o * INF + k4;
        __half* rowp = g_B + (size_t)o * KTOT;
        float4 v; uint2 h;
        v = *reinterpret_cast<const float4*>(C1 + src);
        h.x = pack_h2(v.x, v.y); h.y = pack_h2(v.z, v.w);
        *reinterpret_cast<uint2*>(rowp + k4) = h;
        v = *reinterpret_cast<const float4*>(C2 + src);
        h.x = pack_h2(v.x, v.y); h.y = pack_h2(v.z, v.w);
        *reinterpret_cast<uint2*>(rowp + INF + k4) = h;
        v = *reinterpret_cast<const float4*>(C3 + src);
        h.x = pack_h2(v.x, v.y); h.y = pack_h2(v.z, v.w);
        *reinterpret_cast<uint2*>(rowp + 2 * INF + k4) = h;
    }
}

// ---------------------------------------------------------------------------
// Fully fused: fp16 GEMM (M=4096,N=1024,K=3072) + BN stats + grid barrier +
// BN finalize + normalized store.
// CTA tile 128x256, 512 threads = 16 warps (2m x 8n), warp tile 64x32.
// KCH=64 (4 k16 slabs), 3-stage cp.async pipeline -> 48 syncs (vs 96 in R11),
// PLAIN per-slab fragment loads (R13's reg double-buffering removed: 512 thr
// has a hard 128-reg cap and R11 already sits on it).
// Grid = (4,32) = 128 CTAs at 1 CTA/SM -> co-resident; grid barrier safe.
// ---------------------------------------------------------------------------
#define TILE_M 128
#define TILE_N 256
#define KCH    64
#define NCHUNK (KTOT / KCH)        // 48
#define RBB    144                 // bytes per smem row (128 data + 16 pad)
#define MATB_A (128 * RBB)         // 18432 B
#define MATB_B (256 * RBB)         // 36864 B
#define STAGEB (MATB_A + MATB_B)   // 55296 B
#define SMEM_BYTES (3 * STAGEB)    // 165888 B

__global__ __launch_bounds__(512, 1)
void poly_mma_bn_kernel(float* __restrict__ Y,
                        const float* __restrict__ gamma,
                        const float* __restrict__ beta)
{
    extern __shared__ char sm[];
    const uint32_t smbase = smem_u32(sm);

    const int tid  = threadIdx.x;
    const int wid  = tid >> 5;
    const int lane = tid & 31;
    const int g    = lane >> 2;      // 0..7
    const int tig  = lane & 3;       // 0..3
    const int warp_m = wid >> 3;     // 0..1  -> m base = warp_m*64
    const int warp_n = wid & 7;      // 0..7  -> n base = warp_n*32

    const int block_o = blockIdx.x * TILE_N;
    const int block_b = blockIdx.y * TILE_M;

    // ldmatrix per-lane address components
    const int quad = lane >> 3;
    const int rq   = lane & 7;
    const uint32_t a_lane_off = (uint32_t)((((quad & 1) * 8) + rq) * RBB + (quad >> 1) * 16);
    const uint32_t b_lane_off = (uint32_t)((((quad >> 1) * 8) + rq) * RBB + (quad & 1) * 16);

    // cp.async geometry (512 threads, KCH=64 -> 128B data per row):
    //   A: 128 rows x 8 16B pieces = 1024 -> 2 per thread (pieces qc, qc+4)
    //   B: 256 rows x 8 pieces = 2048 -> 4 per thread (rows r, r+128)
    const int crow = tid >> 2;          // 0..127
    const int qc   = tid & 3;
    const __half* srcA  = g_A + (size_t)(block_b + crow) * KTOT + qc * 8;
    const __half* srcB0 = g_B + (size_t)(block_o + crow) * KTOT + qc * 8;
    const __half* srcB1 = g_B + (size_t)(block_o + crow + 128) * KTOT + qc * 8;
    const uint32_t cdst = (uint32_t)(crow * RBB + qc * 16);

    float acc[4][4][4];
    #pragma unroll
    for (int mt = 0; mt < 4; mt++)
        #pragma unroll
        for (int nt = 0; nt < 4; nt++)
            #pragma unroll
            for (int r = 0; r < 4; r++)
                acc[mt][nt][r] = 0.0f;

    auto stage_chunk = [&](int s) {
        if (s < NCHUNK) {
            const uint32_t base = smbase + (uint32_t)((s % 3) * STAGEB);
            const int k0 = s * KCH;
            cp16(base + cdst,      srcA + k0);
            cp16(base + cdst + 64, srcA + k0 + 32);
            const uint32_t bB = base + MATB_A;
            cp16(bB + cdst,                  srcB0 + k0);
            cp16(bB + cdst + 64,             srcB0 + k0 + 32);
            cp16(bB + cdst + 128 * RBB,      srcB1 + k0);
            cp16(bB + cdst + 128 * RBB + 64, srcB1 + k0 + 32);
        }
        asm volatile("cp.async.commit_group;" ::: "memory");
    };

    stage_chunk(0);
    stage_chunk(1);

    const uint32_t a_warp = (uint32_t)(warp_m * 64 * RBB) + a_lane_off;
    const uint32_t b_warp = (uint32_t)(warp_n * 32 * RBB) + b_lane_off;

    for (int s = 0; s < NCHUNK; ++s) {
        asm volatile("cp.async.wait_group 1;" ::: "memory");
        __syncthreads();

        stage_chunk(s + 2);   // buffer (s+2)%3 == (s-1)%3: freed last iteration

        const uint32_t stA = smbase + (uint32_t)((s % 3) * STAGEB) + a_warp;
        const uint32_t stB = smbase + (uint32_t)((s % 3) * STAGEB) + MATB_A + b_warp;

        #pragma unroll
        for (int kk = 0; kk < 4; kk++) {
            const uint32_t kb = (uint32_t)(kk * 32);

            uint32_t a[4][4];
            #pragma unroll
            for (int mt = 0; mt < 4; mt++)
                LDSM_X4(a[mt][0], a[mt][1], a[mt][2], a[mt][3],
                        stA + (uint32_t)(mt * 16 * RBB) + kb);

            uint32_t b[4][2];
            #pragma unroll
            for (int p = 0; p < 2; p++)
                LDSM_X4(b[2 * p][0], b[2 * p][1], b[2 * p + 1][0], b[2 * p + 1][1],
                        stB + (uint32_t)(p * 16 * RBB) + kb);

            #pragma unroll
            for (int mt = 0; mt < 4; mt++)
                #pragma unroll
                for (int nt = 0; nt < 4; nt++)
                    MMA_F16(acc[mt][nt], a[mt], b[nt]);
        }
    }

    // ---- phase 1: BN partial stats for this 128-row block (registers only)
    float csum[4][2], csq[4][2];
    #pragma unroll
    for (int nt = 0; nt < 4; nt++)
        #pragma unroll
        for (int c = 0; c < 2; c++) {
            float s0 = 0.0f, q0 = 0.0f;
            #pragma unroll
            for (int mt = 0; mt < 4; mt++) {
                const float vlo = acc[mt][nt][c];
                const float vhi = acc[mt][nt][c + 2];
                s0 += vlo + vhi;
                q0 = fmaf(vlo, vlo, q0);
                q0 = fmaf(vhi, vhi, q0);
            }
            csum[nt][c] = s0;
            csq[nt][c] = q0;
        }
    #pragma unroll
    for (int d = 4; d <= 16; d <<= 1) {
        #pragma unroll
        for (int nt = 0; nt < 4; nt++)
            #pragma unroll
            for (int c = 0; c < 2; c++) {
                csum[nt][c] += __shfl_xor_sync(0xFFFFFFFFu, csum[nt][c], d);
                csq[nt][c]  += __shfl_xor_sync(0xFFFFFFFFu, csq[nt][c], d);
            }
    }
    float* red_sum = reinterpret_cast<float*>(sm);          // [2][256]
    float* red_sq  = reinterpret_cast<float*>(sm) + 512;    // [2][256]
    __syncthreads();
    if (g == 0) {
        #pragma unroll
        for (int nt = 0; nt < 4; nt++)
            #pragma unroll
            for (int c = 0; c < 2; c++) {
                const int col = warp_n * 32 + nt * 8 + 2 * tig + c;
                red_sum[warp_m * 256 + col] = csum[nt][c];
                red_sq [warp_m * 256 + col] = csq[nt][c];
            }
    }
    __syncthreads();
    if (tid < 256) {
        g_psum[blockIdx.y][block_o + tid]   = red_sum[tid] + red_sum[256 + tid];
        g_psqsum[blockIdx.y][block_o + tid] = red_sq[tid]  + red_sq[256 + tid];
    }

    // ---- phase 2: grid barrier (replay-safe monotonic ticket).
    // All 128 CTAs co-resident (1 CTA/SM, 128 <= #SMs) -> no deadlock.
    __threadfence();
    __syncthreads();
    if (tid == 0) {
        const unsigned int ticket = atomicAdd(&g_bar, 1u);
        const unsigned int target = (ticket / GRID_CTAS + 1u) * GRID_CTAS;
        while (ld_acquire_gpu(&g_bar) < target) { }
    }
    __syncthreads();

    // ---- phase 3: per-column affine for this CTA's 256 columns
    float* smc = reinterpret_cast<float*>(sm);          // scale [256]
    float* smh = reinterpret_cast<float*>(sm) + 256;    // shift [256]
    if (tid < 256) {
        const int col = block_o + tid;
        float S = 0.0f, SS = 0.0f;
        #pragma unroll
        for (int i = 0; i < 32; i++) { S += g_psum[i][col]; SS += g_psqsum[i][col]; }
        const float inv_n = 1.0f / (float)BATCH;
        const float mean = S * inv_n;
        const float var  = SS * inv_n - mean * mean;
        const float rstd = rsqrtf(var + BN_EPS);
        const float sc = rstd * gamma[col];
        smc[tid] = sc;
        smh[tid] = fmaf(-mean, sc, beta[col]);
    }
    __syncthreads();

    // ---- phase 4: normalize accumulators and store Y once
    #pragma unroll
    for (int mt = 0; mt < 4; mt++) {
        #pragma unroll
        for (int nt = 0; nt < 4; nt++) {
            const int colT = warp_n * 32 + nt * 8 + 2 * tig;
            const float scx = smc[colT],     scy = smc[colT + 1];
            const float shx = smh[colT],     shy = smh[colT + 1];
            const int row = block_b + warp_m * 64 + mt * 16 + g;
            const int col = block_o + colT;
            float2 lo = make_float2(fmaf(acc[mt][nt][0], scx, shx),
                                    fmaf(acc[mt][nt][1], scy, shy));
            float2 hi = make_float2(fmaf(acc[mt][nt][2], scx, shx),
                                    fmaf(acc[mt][nt][3], scy, shy));
            *reinterpret_cast<float2*>(Y + (size_t)row * OUTF + col) = lo;
            *reinterpret_cast<float2*>(Y + (size_t)(row + 8) * OUTF + col) = hi;
        }
    }
}

// ---------------------------------------------------------------------------
// Launcher. Inputs: x, c1, c2, c3, bias(skipped: cancels under BN), gamma, beta
// ---------------------------------------------------------------------------
extern "C" void kernel_launch(void* const* d_in, const int* in_sizes, int n_in,
                              void* d_out, int out_size)
{
    (void)in_sizes; (void)n_in; (void)out_size;
    const float* x     = (const float*)d_in[0];
    const float* c1    = (const float*)d_in[1];
    const float* c2    = (const float*)d_in[2];
    const float* c3    = (const float*)d_in[3];
    const float* gamma = (const float*)d_in[5];
    const float* beta  = (const float*)d_in[6];
    float* y = (float*)d_out;

    cudaFuncSetAttribute(poly_mma_bn_kernel,
                         cudaFuncAttributeMaxDynamicSharedMemorySize, SMEM_BYTES);

    pack_kernel<<<4096 + 1024, 256>>>(x, c1, c2, c3);

    dim3 grid(OUTF / TILE_N, BATCH / TILE_M);   // (4, 32) = 128 CTAs
    poly_mma_bn_kernel<<<grid, 512, SMEM_BYTES>>>(y, gamma, beta);
}

// round 16
// speedup vs baseline: 1.0824x; 1.0216x over previous
#include <cuda_runtime.h>
#include <cuda_fp16.h>
#include <cstdint>
#include <math.h>

// Problem constants: B=4096, OUT=1024, IN=1024
#define BATCH 4096
#define OUTF  1024
#define INF   1024
#define KTOT  3072            // B packing: [c1 | c2 | c3] on K
#define BN_EPS 1e-5f
#define GRID_CTAS 128

// ---------------------------------------------------------------------------
// Scratch (__device__ globals; no allocations allowed)
// ---------------------------------------------------------------------------
__device__ __half g_A[(size_t)BATCH * INF];    //  8 MB: x fp16 (x^2,x^3 derived in regs)
__device__ __half g_B[(size_t)OUTF * KTOT];    //  6 MB: [c1 | c2 | c3] fp16
__device__ float g_psum[32][OUTF];
__device__ float g_psqsum[32][OUTF];
__device__ unsigned int g_bar = 0;             // monotonic grid-barrier ticket

// ---------------------------------------------------------------------------
// Baseline-PTX helpers (sm_80 features only: harness compiles via compute_103)
// ---------------------------------------------------------------------------
__device__ __forceinline__ uint32_t smem_u32(const void* p) {
    uint32_t a;
    asm("{ .reg .u64 t; cvta.to.shared.u64 t, %1; cvt.u32.u64 %0, t; }" : "=r"(a) : "l"(p));
    return a;
}
__device__ __forceinline__ void cp16(uint32_t dst, const void* src) {
    asm volatile("cp.async.cg.shared.global [%0], [%1], 16;" :: "r"(dst), "l"(src));
}
__device__ __forceinline__ uint32_t pack_h2(float lo, float hi) {
    __half2 h = __floats2half2_rn(lo, hi);
    return *reinterpret_cast<uint32_t*>(&h);
}
__device__ __forceinline__ uint32_t hmul2u(uint32_t a, uint32_t b) {
    __half2 r = __hmul2(*reinterpret_cast<__half2*>(&a), *reinterpret_cast<__half2*>(&b));
    return *reinterpret_cast<uint32_t*>(&r);
}
__device__ __forceinline__ unsigned int ld_acquire_gpu(const unsigned int* p) {
    unsigned int v;
    asm volatile("ld.acquire.gpu.u32 %0, [%1];" : "=r"(v) : "l"(p) : "memory");
    return v;
}

// m16n8k16 fp16 tensor-core MMA (sm_80 baseline PTX), fp32 accumulate
#define MMA_F16(d, a, b) \
    asm volatile("mma.sync.aligned.m16n8k16.row.col.f32.f16.f16.f32 " \
        "{%0,%1,%2,%3}, {%4,%5,%6,%7}, {%8,%9}, {%0,%1,%2,%3};" \
        : "+f"((d)[0]), "+f"((d)[1]), "+f"((d)[2]), "+f"((d)[3]) \
        : "r"((a)[0]), "r"((a)[1]), "r"((a)[2]), "r"((a)[3]), \
          "r"((b)[0]), "r"((b)[1]))

// ldmatrix m8n8.x4 (sm_75+ baseline PTX)
#define LDSM_X4(r0, r1, r2, r3, addr) \
    asm volatile("ldmatrix.sync.aligned.m8n8.x4.shared.b16 {%0,%1,%2,%3}, [%4];" \
        : "=r"(r0), "=r"(r1), "=r"(r2), "=r"(r3) : "r"(addr))

// ---------------------------------------------------------------------------
// Pre-pass: pack A = x (fp16) and B = [c1|c2|c3] (fp16).
// Blocks [0,4096) -> A; [4096,5120) -> B.
// ---------------------------------------------------------------------------
__global__ __launch_bounds__(256)
void pack_kernel(const float* __restrict__ X,
                 const float* __restrict__ C1,
                 const float* __restrict__ C2,
                 const float* __restrict__ C3)
{
    if (blockIdx.x < 4096) {
        const int idx = blockIdx.x * 256 + threadIdx.x;
        const int b  = idx >> 8;
        const int k4 = (idx & 255) * 4;
        const float4 v = *reinterpret_cast<const float4*>(X + (size_t)b * INF + k4);
        uint2 h;
        h.x = pack_h2(v.x, v.y); h.y = pack_h2(v.z, v.w);
        *reinterpret_cast<uint2*>(g_A + (size_t)b * INF + k4) = h;
    } else {
        const int idx = (blockIdx.x - 4096) * 256 + threadIdx.x;
        const int o  = idx >> 8;
        const int k4 = (idx & 255) * 4;
        const size_t src = (size_t)o * INF + k4;
        __half* rowp = g_B + (size_t)o * KTOT;
        float4 v; uint2 h;
        v = *reinterpret_cast<const float4*>(C1 + src);
        h.x = pack_h2(v.x, v.y); h.y = pack_h2(v.z, v.w);
        *reinterpret_cast<uint2*>(rowp + k4) = h;
        v = *reinterpret_cast<const float4*>(C2 + src);
        h.x = pack_h2(v.x, v.y); h.y = pack_h2(v.z, v.w);
        *reinterpret_cast<uint2*>(rowp + INF + k4) = h;
        v = *reinterpret_cast<const float4*>(C3 + src);
        h.x = pack_h2(v.x, v.y); h.y = pack_h2(v.z, v.w);
        *reinterpret_cast<uint2*>(rowp + 2 * INF + k4) = h;
    }
}

// ---------------------------------------------------------------------------
// Fully fused polynomial GEMM + BN. K=1024; per k16 slab: load x fragment,
// derive x^2, x^3 in registers (HMUL2), and accumulate 3 MMAs against the
// c1/c2/c3 B tiles loaded sequentially (staggers LDSM through the chunk
// instead of bursting at the barrier -> crossbar hides under MMA issue).
// CTA tile 128x256, 512 threads = 16 warps (2m x 8n), warp tile 64x32.
// KCH=32, 3-stage cp.async pipeline. Grid (4,32)=128 CTAs, 1 CTA/SM,
// co-resident -> software grid barrier safe.
// ---------------------------------------------------------------------------
#define TILE_M 128
#define TILE_N 256
#define KCH    32
#define NCHUNK (INF / KCH)         // 32
#define RBB    80                  // bytes per smem row (64 data + 16 pad)
#define MATB_A (128 * RBB)         // 10240 B (x tile)
#define MATB_B (256 * RBB)         // 20480 B (one c tile)
#define STAGEB (MATB_A + 3 * MATB_B)   // 71680 B
#define SMEM_BYTES (3 * STAGEB)        // 215040 B

__global__ __launch_bounds__(512, 1)
void poly_mma_bn_kernel(float* __restrict__ Y,
                        const float* __restrict__ gamma,
                        const float* __restrict__ beta)
{
    extern __shared__ char sm[];
    const uint32_t smbase = smem_u32(sm);

    const int tid  = threadIdx.x;
    const int wid  = tid >> 5;
    const int lane = tid & 31;
    const int g    = lane >> 2;      // 0..7
    const int tig  = lane & 3;       // 0..3
    const int warp_m = wid >> 3;     // 0..1  -> m base = warp_m*64
    const int warp_n = wid & 7;      // 0..7  -> n base = warp_n*32

    const int block_o = blockIdx.x * TILE_N;
    const int block_b = blockIdx.y * TILE_M;

    // ldmatrix per-lane address components
    const int quad = lane >> 3;
    const int rq   = lane & 7;
    const uint32_t a_lane_off = (uint32_t)((((quad & 1) * 8) + rq) * RBB + (quad >> 1) * 16);
    const uint32_t b_lane_off = (uint32_t)((((quad >> 1) * 8) + rq) * RBB + (quad & 1) * 16);

    // cp.async geometry (512 threads, KCH=32 -> 64B data per row):
    //   A: 128 rows x 4 16B pieces = 512  -> 1 per thread
    //   B: per matrix 256 rows x 4 pieces = 1024 -> 2 per thread; 3 matrices
    const int crow = tid >> 2;          // 0..127
    const int qc   = tid & 3;
    const __half* srcA  = g_A + (size_t)(block_b + crow) * INF + qc * 8;
    const __half* srcB0 = g_B + (size_t)(block_o + crow) * KTOT + qc * 8;
    const __half* srcB1 = g_B + (size_t)(block_o + crow + 128) * KTOT + qc * 8;
    const uint32_t cdst = (uint32_t)(crow * RBB + qc * 16);

    float acc[4][4][4];
    #pragma unroll
    for (int mt = 0; mt < 4; mt++)
        #pragma unroll
        for (int nt = 0; nt < 4; nt++)
            #pragma unroll
            for (int r = 0; r < 4; r++)
                acc[mt][nt][r] = 0.0f;

    auto stage_chunk = [&](int s) {
        if (s < NCHUNK) {
            const uint32_t base = smbase + (uint32_t)((s % 3) * STAGEB);
            const int k0 = s * KCH;
            cp16(base + cdst, srcA + k0);
            #pragma unroll
            for (int m = 0; m < 3; m++) {
                const uint32_t bB = base + MATB_A + (uint32_t)(m * MATB_B);
                const int km = m * INF + k0;
                cp16(bB + cdst,             srcB0 + km);
                cp16(bB + cdst + 128 * RBB, srcB1 + km);
            }
        }
        asm volatile("cp.async.commit_group;" ::: "memory");
    };

    stage_chunk(0);
    stage_chunk(1);

    const uint32_t a_warp = (uint32_t)(warp_m * 64 * RBB) + a_lane_off;
    const uint32_t b_warp = (uint32_t)(warp_n * 32 * RBB) + b_lane_off;

    for (int s = 0; s < NCHUNK; ++s) {
        asm volatile("cp.async.wait_group 1;" ::: "memory");
        __syncthreads();

        stage_chunk(s + 2);   // buffer (s+2)%3 == (s-1)%3: freed last iteration

        const uint32_t base = smbase + (uint32_t)((s % 3) * STAGEB);
        const uint32_t stA  = base + a_warp;
        const uint32_t stB0 = base + MATB_A + b_warp;

        #pragma unroll
        for (int kk = 0; kk < 2; kk++) {
            const uint32_t kb = (uint32_t)(kk * 32);

            // x fragments for this slab (live across all three B passes)
            uint32_t ax[4][4];
            #pragma unroll
            for (int mt = 0; mt < 4; mt++)
                LDSM_X4(ax[mt][0], ax[mt][1], ax[mt][2], ax[mt][3],
                        stA + (uint32_t)(mt * 16 * RBB) + kb);

            // ---- pass 1: c1 with x
            {
                uint32_t bb[4][2];
                #pragma unroll
                for (int p = 0; p < 2; p++)
                    LDSM_X4(bb[2 * p][0], bb[2 * p][1], bb[2 * p + 1][0], bb[2 * p + 1][1],
                            stB0 + (uint32_t)(p * 16 * RBB) + kb);
                #pragma unroll
                for (int mt = 0; mt < 4; mt++)
                    #pragma unroll
                    for (int nt = 0; nt < 4; nt++)
                        MMA_F16(acc[mt][nt], ax[mt], bb[nt]);
            }
            // ---- pass 2: c2 with x^2 (derived per-mt, transient regs)
            {
                uint32_t bb[4][2];
                #pragma unroll
                for (int p = 0; p < 2; p++)
                    LDSM_X4(bb[2 * p][0], bb[2 * p][1], bb[2 * p + 1][0], bb[2 * p + 1][1],
                            stB0 + (uint32_t)(MATB_B) + (uint32_t)(p * 16 * RBB) + kb);
                #pragma unroll
                for (int mt = 0; mt < 4; mt++) {
                    uint32_t x2[4];
                    #pragma unroll
                    for (int r = 0; r < 4; r++) x2[r] = hmul2u(ax[mt][r], ax[mt][r]);
                    #pragma unroll
                    for (int nt = 0; nt < 4; nt++)
                        MMA_F16(acc[mt][nt], x2, bb[nt]);
                }
            }
            // ---- pass 3: c3 with x^3
            {
                uint32_t bb[4][2];
                #pragma unroll
                for (int p = 0; p < 2; p++)
                    LDSM_X4(bb[2 * p][0], bb[2 * p][1], bb[2 * p + 1][0], bb[2 * p + 1][1],
                            stB0 + (uint32_t)(2 * MATB_B) + (uint32_t)(p * 16 * RBB) + kb);
                #pragma unroll
                for (int mt = 0; mt < 4; mt++) {
                    uint32_t x3[4];
                    #pragma unroll
                    for (int r = 0; r < 4; r++) {
                        const uint32_t x2 = hmul2u(ax[mt][r], ax[mt][r]);
                        x3[r] = hmul2u(x2, ax[mt][r]);
                    }
                    #pragma unroll
                    for (int nt = 0; nt < 4; nt++)
                        MMA_F16(acc[mt][nt], x3, bb[nt]);
                }
            }
        }
    }

    // ---- phase 1: BN partial stats for this 128-row block (registers only)
    float csum[4][2], csq[4][2];
    #pragma unroll
    for (int nt = 0; nt < 4; nt++)
        #pragma unroll
        for (int c = 0; c < 2; c++) {
            float s0 = 0.0f, q0 = 0.0f;
            #pragma unroll
            for (int mt = 0; mt < 4; mt++) {
                const float vlo = acc[mt][nt][c];
                const float vhi = acc[mt][nt][c + 2];
                s0 += vlo + vhi;
                q0 = fmaf(vlo, vlo, q0);
                q0 = fmaf(vhi, vhi, q0);
            }
            csum[nt][c] = s0;
            csq[nt][c] = q0;
        }
    #pragma unroll
    for (int d = 4; d <= 16; d <<= 1) {
        #pragma unroll
        for (int nt = 0; nt < 4; nt++)
            #pragma unroll
            for (int c = 0; c < 2; c++) {
                csum[nt][c] += __shfl_xor_sync(0xFFFFFFFFu, csum[nt][c], d);
                csq[nt][c]  += __shfl_xor_sync(0xFFFFFFFFu, csq[nt][c], d);
            }
    }
    float* red_sum = reinterpret_cast<float*>(sm);          // [2][256]
    float* red_sq  = reinterpret_cast<float*>(sm) + 512;    // [2][256]
    __syncthreads();
    if (g == 0) {
        #pragma unroll
        for (int nt = 0; nt < 4; nt++)
            #pragma unroll
            for (int c = 0; c < 2; c++) {
                const int col = warp_n * 32 + nt * 8 + 2 * tig + c;
                red_sum[warp_m * 256 + col] = csum[nt][c];
                red_sq [warp_m * 256 + col] = csq[nt][c];
            }
    }
    __syncthreads();
    if (tid < 256) {
        g_psum[blockIdx.y][block_o + tid]   = red_sum[tid] + red_sum[256 + tid];
        g_psqsum[blockIdx.y][block_o + tid] = red_sq[tid]  + red_sq[256 + tid];
    }

    // ---- phase 2: grid barrier (replay-safe monotonic ticket).
    // All 128 CTAs co-resident (1 CTA/SM, 128 <= #SMs) -> no deadlock.
    __threadfence();
    __syncthreads();
    if (tid == 0) {
        const unsigned int ticket = atomicAdd(&g_bar, 1u);
        const unsigned int target = (ticket / GRID_CTAS + 1u) * GRID_CTAS;
        while (ld_acquire_gpu(&g_bar) < target) { }
    }
    __syncthreads();

    // ---- phase 3: per-column affine for this CTA's 256 columns
    float* smc = reinterpret_cast<float*>(sm);          // scale [256]
    float* smh = reinterpret_cast<float*>(sm) + 256;    // shift [256]
    if (tid < 256) {
        const int col = block_o + tid;
        float S = 0.0f, SS = 0.0f;
        #pragma unroll
        for (int i = 0; i < 32; i++) { S += g_psum[i][col]; SS += g_psqsum[i][col]; }
        const float inv_n = 1.0f / (float)BATCH;
        const float mean = S * inv_n;
        const float var  = SS * inv_n - mean * mean;
        const float rstd = rsqrtf(var + BN_EPS);
        const float sc = rstd * gamma[col];
        smc[tid] = sc;
        smh[tid] = fmaf(-mean, sc, beta[col]);
    }
    __syncthreads();

    // ---- phase 4: normalize accumulators and store Y once
    #pragma unroll
    for (int mt = 0; mt < 4; mt++) {
        #pragma unroll
        for (int nt = 0; nt < 4; nt++) {
            const int colT = warp_n * 32 + nt * 8 + 2 * tig;
            const float scx = smc[colT],     scy = smc[colT + 1];
            const float shx = smh[colT],     shy = smh[colT + 1];
            const int row = block_b + warp_m * 64 + mt * 16 + g;
            const int col = block_o + colT;
            float2 lo = make_float2(fmaf(acc[mt][nt][0], scx, shx),
                                    fmaf(acc[mt][nt][1], scy, shy));
            float2 hi = make_float2(fmaf(acc[mt][nt][2], scx, shx),
                                    fmaf(acc[mt][nt][3], scy, shy));
            *reinterpret_cast<float2*>(Y + (size_t)row * OUTF + col) = lo;
            *reinterpret_cast<float2*>(Y + (size_t)(row + 8) * OUTF + col) = hi;
        }
    }
}

// ---------------------------------------------------------------------------
// Launcher. Inputs: x, c1, c2, c3, bias(skipped: cancels under BN), gamma, beta
// ---------------------------------------------------------------------------
extern "C" void kernel_launch(void* const* d_in, const int* in_sizes, int n_in,
                              void* d_out, int out_size)
{
    (void)in_sizes; (void)n_in; (void)out_size;
    const float* x     = (const float*)d_in[0];
    const float* c1    = (const float*)d_in[1];
    const float* c2    = (const float*)d_in[2];
    const float* c3    = (const float*)d_in[3];
    const float* gamma = (const float*)d_in[5];
    const float* beta  = (const float*)d_in[6];
    float* y = (float*)d_out;

    cudaFuncSetAttribute(poly_mma_bn_kernel,
                         cudaFuncAttributeMaxDynamicSharedMemorySize, SMEM_BYTES);

    pack_kernel<<<4096 + 1024, 256>>>(x, c1, c2, c3);

    dim3 grid(OUTF / TILE_N, BATCH / TILE_M);   // (4, 32) = 128 CTAs
    poly_mma_bn_kernel<<<grid, 512, SMEM_BYTES>>>(y, gamma, beta);
}